// round 14
// baseline (speedup 1.0000x reference)
#include <cuda_runtime.h>
#include <cuda_bf16.h>
#include <cstdint>

#define T_SZ   79
#define HDIM   256
#define MROWS  64
#define NTH    256
#define NCTAS  256           // 256 CTAs * 64 rows = 16384; 2 CTAs/SM

// ---- smem layout (bytes) ----
#define SM_A    0            // A hi [64][512B] swizzled, lo at +32768
#define SM_AX   65536        // x-chunk A: hi [64][32B], lo at +2048
#define SM_BD   69632        // b_d 256 f
#define SM_TOT  70656

// ---- fragment-ordered B images ----
// [chunk][G(16 n16-groups)][lane(32)][16B] = exact mma.m16n8k16 col-B fragment layout
__device__ __align__(16) unsigned char g_U2[2][17 * 8192];  // 0-15: U; 16: [W_in;b_rnn]
__device__ __align__(16) unsigned char g_W2[2][16 * 8192];  // W_d

__global__ void prep_kernel(const float* __restrict__ U, const float* __restrict__ W_in,
                            const float* __restrict__ b_rnn, const float* __restrict__ W_d) {
    int idx = blockIdx.x * blockDim.x + threadIdx.x;
    if (idx >= 33 * 512) return;
    int cimg = idx >> 9;
    int G = (idx >> 5) & 15;
    int l = idx & 31;
    bool isU = (cimg < 17);
    int c = isU ? cimg : cimg - 17;
    uint32_t hi4[4], lo4[4];
#pragma unroll
    for (int f = 0; f < 4; ++f) {
        int n = G * 16 + (l >> 2) + ((f & 2) ? 8 : 0);
        int kk = 2 * (l & 3) + ((f & 1) ? 8 : 0);
        float v[2];
#pragma unroll
        for (int j = 0; j < 2; ++j) {
            int kq = kk + j;
            if (!isU)            v[j] = W_d[(c * 16 + kq) * 256 + n];
            else if (c < 16)     v[j] = U[(c * 16 + kq) * 256 + n];
            else if (kq < 3)     v[j] = W_in[kq * 256 + n];
            else if (kq == 3)    v[j] = b_rnn[n];
            else                 v[j] = 0.0f;
        }
        __nv_bfloat16 h0 = __float2bfloat16_rn(v[0]);
        __nv_bfloat16 h1 = __float2bfloat16_rn(v[1]);
        __nv_bfloat16 l0 = __float2bfloat16_rn(v[0] - __bfloat162float(h0));
        __nv_bfloat16 l1 = __float2bfloat16_rn(v[1] - __bfloat162float(h1));
        hi4[f] = (uint32_t)*(unsigned short*)&h0 | ((uint32_t)*(unsigned short*)&h1 << 16);
        lo4[f] = (uint32_t)*(unsigned short*)&l0 | ((uint32_t)*(unsigned short*)&l1 << 16);
    }
    int off = (c * 16 + G) * 512 + l * 16;
    unsigned char* bh = isU ? g_U2[0] : g_W2[0];
    unsigned char* bl = isU ? g_U2[1] : g_W2[1];
    *(uint4*)(bh + off) = make_uint4(hi4[0], hi4[1], hi4[2], hi4[3]);
    *(uint4*)(bl + off) = make_uint4(lo4[0], lo4[1], lo4[2], lo4[3]);
}

// ---- PTX helpers ----
__device__ __forceinline__ uint32_t smem_u32(const void* p) {
    uint32_t a;
    asm("{ .reg .u64 t; cvta.to.shared.u64 t, %1; cvt.u32.u64 %0, t; }" : "=r"(a) : "l"(p));
    return a;
}
__device__ __forceinline__ void ldsm4(uint32_t r[4], uint32_t addr) {
    asm volatile("ldmatrix.sync.aligned.m8n8.x4.shared.b16 {%0,%1,%2,%3}, [%4];"
                 : "=r"(r[0]), "=r"(r[1]), "=r"(r[2]), "=r"(r[3]) : "r"(addr));
}
__device__ __forceinline__ void mma16816(float d[4], const uint32_t a[4],
                                         uint32_t b0, uint32_t b1) {
    asm volatile("mma.sync.aligned.m16n8k16.row.col.f32.bf16.bf16.f32 "
                 "{%0,%1,%2,%3}, {%4,%5,%6,%7}, {%8,%9}, {%0,%1,%2,%3};"
                 : "+f"(d[0]), "+f"(d[1]), "+f"(d[2]), "+f"(d[3])
                 : "r"(a[0]), "r"(a[1]), "r"(a[2]), "r"(a[3]), "r"(b0), "r"(b1));
}

struct TileCtx { uint32_t sb; int tid, lane, m0, nb; };

// A fragments for chunk c (c==16 -> x-chunk from SM_AX)
__device__ __forceinline__ void loadA(const TileCtx& cx, int c,
                                      uint32_t Ah[2][4], uint32_t Al[2][4]) {
    const int hb = (cx.lane >> 4) & 1;
#pragma unroll
    for (int mt = 0; mt < 2; ++mt) {
        int mrow = cx.m0 + mt * 16 + (cx.lane & 15);
        if (c < 16) {
            uint32_t boff = (uint32_t)(c * 32 + hb * 16) ^ ((mrow & 7) << 4);
            uint32_t a0 = cx.sb + SM_A + mrow * 512 + boff;
            ldsm4(Ah[mt], a0);
            ldsm4(Al[mt], a0 + 32768);
        } else {
            uint32_t a0 = cx.sb + SM_AX + mrow * 32 + hb * 16;
            ldsm4(Ah[mt], a0);
            ldsm4(Al[mt], a0 + 2048);
        }
    }
}

// one n16 unit: 12 MMAs (Ah*Bh, Ah*Bl, Al*Bh)
__device__ __forceinline__ void mma_unit(float D[2][8][4], const uint32_t Ah[2][4],
                                         const uint32_t Al[2][4],
                                         const uint4& bh, const uint4& bl, int ng) {
#pragma unroll
    for (int mt = 0; mt < 2; ++mt) {
        mma16816(D[mt][2 * ng],     Ah[mt], bh.x, bh.y);
        mma16816(D[mt][2 * ng + 1], Ah[mt], bh.z, bh.w);
    }
#pragma unroll
    for (int mt = 0; mt < 2; ++mt) {
        mma16816(D[mt][2 * ng],     Ah[mt], bl.x, bl.y);
        mma16816(D[mt][2 * ng + 1], Ah[mt], bl.z, bl.w);
    }
#pragma unroll
    for (int mt = 0; mt < 2; ++mt) {
        mma16816(D[mt][2 * ng],     Al[mt], bh.x, bh.y);
        mma16816(D[mt][2 * ng + 1], Al[mt], bh.z, bh.w);
    }
}

// stream chunks [c0, nchunks); B fragments from global with distance-1 prefetch
__device__ __forceinline__ void stream_chunks(const TileCtx& cx, float D[2][8][4],
        const unsigned char* __restrict__ ih, const unsigned char* __restrict__ il,
        int c0, int nchunks) {
    uint32_t Ah[2][4], Al[2][4];
    const uint32_t lb = (uint32_t)((cx.nb >> 4) * 512 + cx.lane * 16);
    uint4 Bh[2], Bl[2];
    loadA(cx, c0, Ah, Al);
    Bh[0] = *(const uint4*)(ih + (uint32_t)c0 * 8192 + lb);
    Bl[0] = *(const uint4*)(il + (uint32_t)c0 * 8192 + lb);
    for (int c = c0; c < nchunks; ++c) {
        uint32_t cb = (uint32_t)c * 8192 + lb;
#pragma unroll
        for (int ng = 0; ng < 4; ++ng) {
            bool last = (c == nchunks - 1) && (ng == 3);
            if (!last) {
                uint32_t o = (ng < 3) ? (cb + (ng + 1) * 512) : (cb + 8192);
                Bh[(ng + 1) & 1] = *(const uint4*)(ih + o);
                Bl[(ng + 1) & 1] = *(const uint4*)(il + o);
            }
            mma_unit(D, Ah, Al, Bh[ng & 1], Bl[ng & 1], ng);
            if (ng == 3 && c + 1 < nchunks) loadA(cx, c + 1, Ah, Al);
        }
    }
}

__global__ void __launch_bounds__(NTH, 2)
rnn_mma_kernel(const float* __restrict__ x0, const float* __restrict__ x1,
               const float* __restrict__ x2, const float* __restrict__ b_d,
               float* __restrict__ out) {
    extern __shared__ __align__(1024) unsigned char smem[];
    TileCtx cx;
    cx.sb = smem_u32(smem);
    cx.tid = threadIdx.x;
    cx.lane = cx.tid & 31;
    const int w = cx.tid >> 5;          // 0..7
    cx.m0 = (w & 1) * 32;
    cx.nb = (w >> 1) * 64;
    const int row_base = blockIdx.x * MROWS;

    // init: zero A (h0=0) and Ax; bias col (k=3)=1.0 in Ax-hi; b_d -> smem
    for (int i = cx.tid; i < 65536 / 4; i += NTH) ((uint32_t*)(smem + SM_A))[i] = 0;
    for (int i = cx.tid; i < 4096 / 4; i += NTH) ((uint32_t*)(smem + SM_AX))[i] = 0;
    __syncthreads();
    if (cx.tid < 64) *(unsigned short*)(smem + SM_AX + cx.tid * 32 + 6) = 0x3F80;
    ((float*)(smem + SM_BD))[cx.tid] = b_d[cx.tid];   // 256 threads = 256 values

    // x prefetch: thread (row, f) owns one value per step; publish x(t=0)
    const int xrow = cx.tid >> 2, xf = cx.tid & 3;    // xrow 0..63
    const bool xact = (xf < 3);
    const float* xbase = (xf == 0) ? x0 : (xf == 1) ? x1 : x2;
    if (xact) {
        float v = xbase[(size_t)(row_base + xrow) * T_SZ + (T_SZ - 1)];
        __nv_bfloat16 h = __float2bfloat16_rn(v);
        __nv_bfloat16 l = __float2bfloat16_rn(v - __bfloat162float(h));
        *(unsigned short*)(smem + SM_AX + xrow * 32 + xf * 2) = *(unsigned short*)&h;
        *(unsigned short*)(smem + SM_AX + 2048 + xrow * 32 + xf * 2) = *(unsigned short*)&l;
    }
    float xv = 0.0f;
    if (xact) xv = xbase[(size_t)(row_base + xrow) * T_SZ + (T_SZ - 2)];
    __syncthreads();

    float D[2][8][4];
#pragma unroll
    for (int mt = 0; mt < 2; ++mt)
#pragma unroll
        for (int nt = 0; nt < 8; ++nt)
#pragma unroll
            for (int e = 0; e < 4; ++e) D[mt][nt][e] = 0.0f;

#pragma unroll 1
    for (int t = 0; t < T_SZ; ++t) {
        // t=0: h=0, only the x-chunk (16) contributes
        stream_chunks(cx, D, g_U2[0], g_U2[1], (t == 0) ? 16 : 0, 17);
        __syncthreads();                              // all A/Ax reads done

        if (xact && t + 1 < T_SZ) {                   // publish next x
            __nv_bfloat16 h = __float2bfloat16_rn(xv);
            __nv_bfloat16 l = __float2bfloat16_rn(xv - __bfloat162float(h));
            *(unsigned short*)(smem + SM_AX + xrow * 32 + xf * 2) = *(unsigned short*)&h;
            *(unsigned short*)(smem + SM_AX + 2048 + xrow * 32 + xf * 2) = *(unsigned short*)&l;
            if (t + 2 < T_SZ)
                xv = xbase[(size_t)(row_base + xrow) * T_SZ + (T_SZ - 3 - t)];
        }
        // epilogue: h = relu(D) -> split -> A (swizzled); zero D
#pragma unroll
        for (int mt = 0; mt < 2; ++mt) {
            int mA = cx.m0 + mt * 16 + (cx.lane >> 2);
#pragma unroll
            for (int nt = 0; nt < 8; ++nt) {
                int n = cx.nb + nt * 8 + 2 * (cx.lane & 3);
#pragma unroll
                for (int half = 0; half < 2; ++half) {
                    int m = mA + half * 8;
                    float v0 = fmaxf(D[mt][nt][2 * half], 0.0f);
                    float v1 = fmaxf(D[mt][nt][2 * half + 1], 0.0f);
                    uint32_t hp;
                    asm("cvt.rn.bf16x2.f32 %0, %1, %2;" : "=r"(hp) : "f"(v1), "f"(v0));
                    float h0 = __uint_as_float(hp << 16);
                    float h1 = __uint_as_float(hp & 0xFFFF0000u);
                    uint32_t lp;
                    asm("cvt.rn.bf16x2.f32 %0, %1, %2;" : "=r"(lp) : "f"(v1 - h1), "f"(v0 - h0));
                    uint32_t off = (uint32_t)(2 * n) ^ ((m & 7) << 4);
                    *(uint32_t*)(smem + SM_A + m * 512 + off) = hp;
                    *(uint32_t*)(smem + SM_A + 32768 + m * 512 + off) = lp;
                }
            }
        }
#pragma unroll
        for (int mt = 0; mt < 2; ++mt)
#pragma unroll
            for (int nt = 0; nt < 8; ++nt)
#pragma unroll
                for (int e = 0; e < 4; ++e) D[mt][nt][e] = 0.0f;
        __syncthreads();                              // A rewrite visible
    }

    // final GEMM: out = hT @ W_d + b_d
    stream_chunks(cx, D, g_W2[0], g_W2[1], 0, 16);
    const float* bd = (const float*)(smem + SM_BD);
#pragma unroll
    for (int mt = 0; mt < 2; ++mt) {
        int mA = cx.m0 + mt * 16 + (cx.lane >> 2);
#pragma unroll
        for (int nt = 0; nt < 8; ++nt) {
            int n = cx.nb + nt * 8 + 2 * (cx.lane & 3);
            float b0 = bd[n], b1 = bd[n + 1];
#pragma unroll
            for (int half = 0; half < 2; ++half) {
                int m = mA + half * 8;
                float2 o = make_float2(D[mt][nt][2 * half] + b0, D[mt][nt][2 * half + 1] + b1);
                *(float2*)(out + (size_t)(row_base + m) * HDIM + n) = o;
            }
        }
    }
}

extern "C" void kernel_launch(void* const* d_in, const int* in_sizes, int n_in,
                              void* d_out, int out_size) {
    (void)in_sizes; (void)n_in; (void)out_size;
    const float* x0    = (const float*)d_in[0];
    const float* x1    = (const float*)d_in[1];
    const float* x2    = (const float*)d_in[2];
    const float* W_in  = (const float*)d_in[3];
    const float* U     = (const float*)d_in[4];
    const float* b_rnn = (const float*)d_in[5];
    const float* W_d   = (const float*)d_in[6];
    const float* b_d   = (const float*)d_in[7];
    float* out = (float*)d_out;

    prep_kernel<<<66, 256>>>(U, W_in, b_rnn, W_d);

    cudaFuncSetAttribute(rnn_mma_kernel,
                         cudaFuncAttributeMaxDynamicSharedMemorySize, SM_TOT);
    rnn_mma_kernel<<<NCTAS, NTH, SM_TOT>>>(x0, x1, x2, b_d, out);
}

// round 15
// speedup vs baseline: 1.0285x; 1.0285x over previous
#include <cuda_runtime.h>
#include <cuda_bf16.h>
#include <cstdint>

#define T_SZ   79
#define HDIM   256
#define MROWS  128
#define NTH    512
#define NCTAS  128

// ---- smem layout (bytes) ----
#define SM_A    0          // A hi [128][512B] swizzled, lo at +65536
#define SM_AX   131072     // x-chunk A: hi [128][32B], lo at +4096
#define SM_BD   139264     // b_d 256 f
#define SM_TOT  140288

// ---- fragment-ordered B images ----
// [chunk][G(16 n16-groups)][lane(32)][16B] = exact mma.m16n8k16 col-B fragment layout
__device__ __align__(16) unsigned char g_U2[2][17 * 8192];  // 0-15: U; 16: [W_in;b_rnn]
__device__ __align__(16) unsigned char g_W2[2][16 * 8192];  // W_d

__global__ void prep_kernel(const float* __restrict__ U, const float* __restrict__ W_in,
                            const float* __restrict__ b_rnn, const float* __restrict__ W_d) {
    int idx = blockIdx.x * blockDim.x + threadIdx.x;
    if (idx >= 33 * 512) return;
    int cimg = idx >> 9;
    int G = (idx >> 5) & 15;
    int l = idx & 31;
    bool isU = (cimg < 17);
    int c = isU ? cimg : cimg - 17;
    uint32_t hi4[4], lo4[4];
#pragma unroll
    for (int f = 0; f < 4; ++f) {
        int n = G * 16 + (l >> 2) + ((f & 2) ? 8 : 0);
        int kk = 2 * (l & 3) + ((f & 1) ? 8 : 0);
        float v[2];
#pragma unroll
        for (int j = 0; j < 2; ++j) {
            int kq = kk + j;
            if (!isU)            v[j] = W_d[(c * 16 + kq) * 256 + n];
            else if (c < 16)     v[j] = U[(c * 16 + kq) * 256 + n];
            else if (kq < 3)     v[j] = W_in[kq * 256 + n];
            else if (kq == 3)    v[j] = b_rnn[n];
            else                 v[j] = 0.0f;
        }
        __nv_bfloat16 h0 = __float2bfloat16_rn(v[0]);
        __nv_bfloat16 h1 = __float2bfloat16_rn(v[1]);
        __nv_bfloat16 l0 = __float2bfloat16_rn(v[0] - __bfloat162float(h0));
        __nv_bfloat16 l1 = __float2bfloat16_rn(v[1] - __bfloat162float(h1));
        hi4[f] = (uint32_t)*(unsigned short*)&h0 | ((uint32_t)*(unsigned short*)&h1 << 16);
        lo4[f] = (uint32_t)*(unsigned short*)&l0 | ((uint32_t)*(unsigned short*)&l1 << 16);
    }
    int off = (c * 16 + G) * 512 + l * 16;
    unsigned char* bh = isU ? g_U2[0] : g_W2[0];
    unsigned char* bl = isU ? g_U2[1] : g_W2[1];
    *(uint4*)(bh + off) = make_uint4(hi4[0], hi4[1], hi4[2], hi4[3]);
    *(uint4*)(bl + off) = make_uint4(lo4[0], lo4[1], lo4[2], lo4[3]);
}

// ---- PTX helpers ----
__device__ __forceinline__ uint32_t smem_u32(const void* p) {
    uint32_t a;
    asm("{ .reg .u64 t; cvta.to.shared.u64 t, %1; cvt.u32.u64 %0, t; }" : "=r"(a) : "l"(p));
    return a;
}
__device__ __forceinline__ void ldsm4(uint32_t r[4], uint32_t addr) {
    asm volatile("ldmatrix.sync.aligned.m8n8.x4.shared.b16 {%0,%1,%2,%3}, [%4];"
                 : "=r"(r[0]), "=r"(r[1]), "=r"(r[2]), "=r"(r[3]) : "r"(addr));
}
__device__ __forceinline__ void mma16816(float d[4], const uint32_t a[4],
                                         uint32_t b0, uint32_t b1) {
    asm volatile("mma.sync.aligned.m16n8k16.row.col.f32.bf16.bf16.f32 "
                 "{%0,%1,%2,%3}, {%4,%5,%6,%7}, {%8,%9}, {%0,%1,%2,%3};"
                 : "+f"(d[0]), "+f"(d[1]), "+f"(d[2]), "+f"(d[3])
                 : "r"(a[0]), "r"(a[1]), "r"(a[2]), "r"(a[3]), "r"(b0), "r"(b1));
}
__device__ __forceinline__ void prefL1(const unsigned char* p) {
    asm volatile("prefetch.global.L1 [%0];" :: "l"(p));
}

struct TileCtx { uint32_t sb; int tid, lane, m0, nb; };

// A fragments for chunk c (c==16 -> x-chunk from SM_AX)
__device__ __forceinline__ void loadA(const TileCtx& cx, int c,
                                      uint32_t Ah[2][4], uint32_t Al[2][4]) {
    const int hb = (cx.lane >> 4) & 1;
#pragma unroll
    for (int mt = 0; mt < 2; ++mt) {
        int mrow = cx.m0 + mt * 16 + (cx.lane & 15);
        if (c < 16) {
            uint32_t boff = (uint32_t)(c * 32 + hb * 16) ^ ((mrow & 7) << 4);
            uint32_t a0 = cx.sb + SM_A + mrow * 512 + boff;
            ldsm4(Ah[mt], a0);
            ldsm4(Al[mt], a0 + 65536);
        } else {
            uint32_t a0 = cx.sb + SM_AX + mrow * 32 + hb * 16;
            ldsm4(Ah[mt], a0);
            ldsm4(Al[mt], a0 + 4096);
        }
    }
}

// one n16 unit: 12 MMAs (Ah*Bh, Ah*Bl, Al*Bh)
__device__ __forceinline__ void mma_unit(float D[2][8][4], const uint32_t Ah[2][4],
                                         const uint32_t Al[2][4],
                                         const uint4& bh, const uint4& bl, int ng) {
#pragma unroll
    for (int mt = 0; mt < 2; ++mt) {
        mma16816(D[mt][2 * ng],     Ah[mt], bh.x, bh.y);
        mma16816(D[mt][2 * ng + 1], Ah[mt], bh.z, bh.w);
    }
#pragma unroll
    for (int mt = 0; mt < 2; ++mt) {
        mma16816(D[mt][2 * ng],     Ah[mt], bl.x, bl.y);
        mma16816(D[mt][2 * ng + 1], Ah[mt], bl.z, bl.w);
    }
#pragma unroll
    for (int mt = 0; mt < 2; ++mt) {
        mma16816(D[mt][2 * ng],     Al[mt], bh.x, bh.y);
        mma16816(D[mt][2 * ng + 1], Al[mt], bh.z, bh.w);
    }
}

// stream chunks [c0, nchunks); register ring distance-1 + L1 prefetch distance-3
__device__ __forceinline__ void stream_chunks(const TileCtx& cx, float D[2][8][4],
        const unsigned char* __restrict__ ih, const unsigned char* __restrict__ il,
        int c0, int nchunks) {
    uint32_t Ah[2][4], Al[2][4];
    const uint32_t lb = (uint32_t)((cx.nb >> 4) * 512 + cx.lane * 16);
    uint4 Bh[2], Bl[2];
    loadA(cx, c0, Ah, Al);
    Bh[0] = *(const uint4*)(ih + (uint32_t)c0 * 8192 + lb);
    Bl[0] = *(const uint4*)(il + (uint32_t)c0 * 8192 + lb);
    // prime L1 for the first few positions
#pragma unroll
    for (int q = 1; q < 4; ++q) {
        int pp = 4 * c0 + q;
        if (pp < 4 * nchunks) {
            uint32_t o = (uint32_t)(pp >> 2) * 8192 + (uint32_t)(pp & 3) * 512 + lb;
            prefL1(ih + o); prefL1(il + o);
        }
    }
    for (int c = c0; c < nchunks; ++c) {
        uint32_t cb = (uint32_t)c * 8192 + lb;
#pragma unroll
        for (int ng = 0; ng < 4; ++ng) {
            // L1 prefetch 3 positions ahead (~288 cyc of MMA cover >= L2 RT)
            int pp = 4 * c + ng + 4;
            if (pp < 4 * nchunks) {
                uint32_t o = (uint32_t)(pp >> 2) * 8192 + (uint32_t)(pp & 3) * 512 + lb;
                prefL1(ih + o); prefL1(il + o);
            }
            bool last = (c == nchunks - 1) && (ng == 3);
            if (!last) {
                uint32_t o = (ng < 3) ? (cb + (ng + 1) * 512) : (cb + 8192);
                Bh[(ng + 1) & 1] = *(const uint4*)(ih + o);
                Bl[(ng + 1) & 1] = *(const uint4*)(il + o);
            }
            mma_unit(D, Ah, Al, Bh[ng & 1], Bl[ng & 1], ng);
            if (ng == 3 && c + 1 < nchunks) loadA(cx, c + 1, Ah, Al);
        }
    }
}

__global__ void __launch_bounds__(NTH, 1)
rnn_mma_kernel(const float* __restrict__ x0, const float* __restrict__ x1,
               const float* __restrict__ x2, const float* __restrict__ b_d,
               float* __restrict__ out) {
    extern __shared__ __align__(1024) unsigned char smem[];
    TileCtx cx;
    cx.sb = smem_u32(smem);
    cx.tid = threadIdx.x;
    cx.lane = cx.tid & 31;
    const int w = cx.tid >> 5;
    cx.m0 = (w & 3) * 32;
    cx.nb = (w >> 2) * 64;
    const int row_base = blockIdx.x * MROWS;

    // init: zero A (h0=0) and Ax; bias col (k=3)=1.0 in Ax-hi; b_d -> smem
    for (int i = cx.tid; i < 131072 / 4; i += NTH) ((uint32_t*)(smem + SM_A))[i] = 0;
    for (int i = cx.tid; i < 8192 / 4; i += NTH) ((uint32_t*)(smem + SM_AX))[i] = 0;
    __syncthreads();
    if (cx.tid < 128) *(unsigned short*)(smem + SM_AX + cx.tid * 32 + 6) = 0x3F80;
    if (cx.tid < 256) ((float*)(smem + SM_BD))[cx.tid] = b_d[cx.tid];

    // x prefetch: thread (row, f) owns one value per step; publish x(t=0)
    const int xrow = cx.tid >> 2, xf = cx.tid & 3;
    const bool xact = (xf < 3);
    const float* xbase = (xf == 0) ? x0 : (xf == 1) ? x1 : x2;
    if (xact) {
        float v = xbase[(size_t)(row_base + xrow) * T_SZ + (T_SZ - 1)];
        __nv_bfloat16 h = __float2bfloat16_rn(v);
        __nv_bfloat16 l = __float2bfloat16_rn(v - __bfloat162float(h));
        *(unsigned short*)(smem + SM_AX + xrow * 32 + xf * 2) = *(unsigned short*)&h;
        *(unsigned short*)(smem + SM_AX + 4096 + xrow * 32 + xf * 2) = *(unsigned short*)&l;
    }
    float xv = 0.0f;
    if (xact) xv = xbase[(size_t)(row_base + xrow) * T_SZ + (T_SZ - 2)];
    __syncthreads();

    float D[2][8][4];
#pragma unroll
    for (int mt = 0; mt < 2; ++mt)
#pragma unroll
        for (int nt = 0; nt < 8; ++nt)
#pragma unroll
            for (int e = 0; e < 4; ++e) D[mt][nt][e] = 0.0f;

#pragma unroll 1
    for (int t = 0; t < T_SZ; ++t) {
        // t=0: h=0, only the x-chunk (16) contributes
        stream_chunks(cx, D, g_U2[0], g_U2[1], (t == 0) ? 16 : 0, 17);
        __syncthreads();                              // all A/Ax reads done

        if (xact && t + 1 < T_SZ) {                   // publish next x
            __nv_bfloat16 h = __float2bfloat16_rn(xv);
            __nv_bfloat16 l = __float2bfloat16_rn(xv - __bfloat162float(h));
            *(unsigned short*)(smem + SM_AX + xrow * 32 + xf * 2) = *(unsigned short*)&h;
            *(unsigned short*)(smem + SM_AX + 4096 + xrow * 32 + xf * 2) = *(unsigned short*)&l;
            if (t + 2 < T_SZ)
                xv = xbase[(size_t)(row_base + xrow) * T_SZ + (T_SZ - 3 - t)];
        }
        // epilogue: h = relu(D) -> split -> A (swizzled); zero D
#pragma unroll
        for (int mt = 0; mt < 2; ++mt) {
            int mA = cx.m0 + mt * 16 + (cx.lane >> 2);
#pragma unroll
            for (int nt = 0; nt < 8; ++nt) {
                int n = cx.nb + nt * 8 + 2 * (cx.lane & 3);
#pragma unroll
                for (int half = 0; half < 2; ++half) {
                    int m = mA + half * 8;
                    float v0 = fmaxf(D[mt][nt][2 * half], 0.0f);
                    float v1 = fmaxf(D[mt][nt][2 * half + 1], 0.0f);
                    uint32_t hp;
                    asm("cvt.rn.bf16x2.f32 %0, %1, %2;" : "=r"(hp) : "f"(v1), "f"(v0));
                    float h0 = __uint_as_float(hp << 16);
                    float h1 = __uint_as_float(hp & 0xFFFF0000u);
                    uint32_t lp;
                    asm("cvt.rn.bf16x2.f32 %0, %1, %2;" : "=r"(lp) : "f"(v1 - h1), "f"(v0 - h0));
                    uint32_t off = (uint32_t)(2 * n) ^ ((m & 7) << 4);
                    *(uint32_t*)(smem + SM_A + m * 512 + off) = hp;
                    *(uint32_t*)(smem + SM_A + 65536 + m * 512 + off) = lp;
                }
            }
        }
#pragma unroll
        for (int mt = 0; mt < 2; ++mt)
#pragma unroll
            for (int nt = 0; nt < 8; ++nt)
#pragma unroll
                for (int e = 0; e < 4; ++e) D[mt][nt][e] = 0.0f;
        __syncthreads();                              // A rewrite visible
    }

    // final GEMM: out = hT @ W_d + b_d
    stream_chunks(cx, D, g_W2[0], g_W2[1], 0, 16);
    const float* bd = (const float*)(smem + SM_BD);
#pragma unroll
    for (int mt = 0; mt < 2; ++mt) {
        int mA = cx.m0 + mt * 16 + (cx.lane >> 2);
#pragma unroll
        for (int nt = 0; nt < 8; ++nt) {
            int n = cx.nb + nt * 8 + 2 * (cx.lane & 3);
            float b0 = bd[n], b1 = bd[n + 1];
#pragma unroll
            for (int half = 0; half < 2; ++half) {
                int m = mA + half * 8;
                float2 o = make_float2(D[mt][nt][2 * half] + b0, D[mt][nt][2 * half + 1] + b1);
                *(float2*)(out + (size_t)(row_base + m) * HDIM + n) = o;
            }
        }
    }
}

extern "C" void kernel_launch(void* const* d_in, const int* in_sizes, int n_in,
                              void* d_out, int out_size) {
    (void)in_sizes; (void)n_in; (void)out_size;
    const float* x0    = (const float*)d_in[0];
    const float* x1    = (const float*)d_in[1];
    const float* x2    = (const float*)d_in[2];
    const float* W_in  = (const float*)d_in[3];
    const float* U     = (const float*)d_in[4];
    const float* b_rnn = (const float*)d_in[5];
    const float* W_d   = (const float*)d_in[6];
    const float* b_d   = (const float*)d_in[7];
    float* out = (float*)d_out;

    prep_kernel<<<66, 256>>>(U, W_in, b_rnn, W_d);

    cudaFuncSetAttribute(rnn_mma_kernel,
                         cudaFuncAttributeMaxDynamicSharedMemorySize, SM_TOT);
    rnn_mma_kernel<<<NCTAS, NTH, SM_TOT>>>(x0, x1, x2, b_d, out);
}